// round 10
// baseline (speedup 1.0000x reference)
#include <cuda_runtime.h>
#include <math.h>

#define NBATCH 8
#define DPIX   147456     // 384*384
#define KBINS  256
#define BINS   50

// Scratch (device globals; no dynamic allocation allowed)
__device__ __align__(16) float g_A[NBATCH * KBINS * KBINS];  // fine 2D histogram (2 MB)
__device__ __align__(16) float g_G [BINS * KBINS];           // G[b][i]
__device__ __align__(16) float g_GT[KBINS * BINS];           // GT[i][b]
__device__ __align__(16) float g_P [2 * NBATCH * BINS * KBINS];  // P halves [is][n][b][j]
__device__ __align__(16) float g_hgram[NBATCH * BINS * BINS];
__device__ float g_mx[NBATCH * BINS];       // row marginals
__device__ unsigned int g_cnt;              // stageD arrival counter (self-resetting)

// ---------------- Kernel 1: zero histogram + precompute soft-bin kernel G -----
__global__ void k_init() {
    int gid = blockIdx.x * blockDim.x + threadIdx.x;
    int stride = gridDim.x * blockDim.x;

    float4 z = make_float4(0.f, 0.f, 0.f, 0.f);
    float4* A4 = (float4*)g_A;
    int totA = (NBATCH * KBINS * KBINS) / 4;
    for (int t = gid; t < totA; t += stride) A4[t] = z;

    for (int t = gid; t < BINS * KBINS; t += stride) {
        int b = t / KBINS, i = t % KBINS;
        double x = (i + 0.5) / (double)KBINS;
        double c = (b + 0.5) * 0.02;
        double d = 10.0 * (x - c);
        double s1 = 1.0 / (1.0 + exp(-(d + 0.1)));
        double s2 = 1.0 / (1.0 + exp(-(d - 0.1)));
        float v = (float)(s1 - s2);
        g_G [b * KBINS + i] = v;
        g_GT[i * BINS  + b] = v;
    }
}

// ---------------- Kernel 2: nearest-cell 2D histogram (1 scalar RED / pixel) --
__device__ __forceinline__ void red1(float* p, float a) {
    asm volatile("red.global.add.f32 [%0], %1;" :: "l"(p), "f"(a) : "memory");
}

__global__ void k_hist(const float* __restrict__ im1, const float* __restrict__ im2) {
    int gid = blockIdx.x * blockDim.x + threadIdx.x;   // one float4 chunk (4 pixels)
    const int nchunk = (NBATCH * DPIX) / 4;
    if (gid >= nchunk) return;
    int n = gid / (DPIX / 4);   // 36864 chunks per batch, no straddle
    float4 xv = ((const float4*)im1)[gid];
    float4 yv = ((const float4*)im2)[gid];
    float* base = g_A + (size_t)n * KBINS * KBINS;

    float xs[4] = {xv.x, xv.y, xv.z, xv.w};
    float ys[4] = {yv.x, yv.y, yv.z, yv.w};
#pragma unroll
    for (int q = 0; q < 4; q++) {
        int i0 = min(KBINS - 1, (int)(xs[q] * 256.0f));
        int j0 = min(KBINS - 1, (int)(ys[q] * 256.0f));
        red1(base + i0 * KBINS + j0, 1.0f);
    }
}

// ---------------- Kernel 3: P[is][n][b][j] = sum_{i in half} G[b][i]*H[n][i][j]
// grid = 160 blocks, 128 threads
__global__ void k_stageC() {
    int blk = blockIdx.x;
    int n  = blk / 20;
    int r  = blk % 20;
    int jt = r / 10;
    int r2 = r % 10;
    int bg = r2 / 2, is = r2 % 2;
    int j  = jt * 128 + threadIdx.x;
    int b0 = bg * 10;
    int i_beg = is * 128;

    __shared__ float Gs[64][12];   // 48B rows -> float4-aligned
    float acc[10];
#pragma unroll
    for (int k = 0; k < 10; k++) acc[k] = 0.0f;

    const float* A = g_A + (size_t)n * KBINS * KBINS + j;

    for (int it = i_beg; it < i_beg + 128; it += 64) {
        __syncthreads();
        for (int t = threadIdx.x; t < 640; t += 128) {
            int ii = t / 10, k = t % 10;
            Gs[ii][k] = g_GT[(it + ii) * BINS + b0 + k];
        }
        __syncthreads();
#pragma unroll 8
        for (int ii = 0; ii < 64; ii++) {
            int i = it + ii;
            float h = A[(size_t)i * KBINS];
            float4 ga = *(const float4*)&Gs[ii][0];
            float4 gb = *(const float4*)&Gs[ii][4];
            float2 gc = *(const float2*)&Gs[ii][8];
            acc[0] += h * ga.x; acc[1] += h * ga.y; acc[2] += h * ga.z; acc[3] += h * ga.w;
            acc[4] += h * gb.x; acc[5] += h * gb.y; acc[6] += h * gb.z; acc[7] += h * gb.w;
            acc[8] += h * gc.x; acc[9] += h * gc.y;
        }
    }
    size_t pb = (((size_t)is * NBATCH + n) * BINS + b0) * KBINS + j;
#pragma unroll
    for (int k = 0; k < 10; k++) g_P[pb + (size_t)k * KBINS] = acc[k];
}

// ---------------- Kernel 4: hgram rows + last-block MI tail -------------------
// grid = 400 (nb = n*50+b), 256 threads: tid = g*64 + c
__global__ void __launch_bounds__(256) k_stageD(float* __restrict__ out) {
    int nb = blockIdx.x;
    __shared__ float Ps[KBINS];
    __shared__ float part[4][64];
    __shared__ float rows[64];
    int tid = threadIdx.x;
    int g = tid >> 6, c = tid & 63;

    // stage Ps: 256 coalesced scalar loads per half
    Ps[tid] = g_P[(size_t)nb * KBINS + tid]
            + g_P[(size_t)(NBATCH * BINS + nb) * KBINS + tid];
    __syncthreads();

    float s = 0.0f;
    if (c < BINS) {
        const float* GTc = g_GT + c;
        int j0 = g * 64;
        float a0 = 0.f, a1 = 0.f, a2 = 0.f, a3 = 0.f;
#pragma unroll
        for (int j = 0; j < 64; j += 4) {
            a0 += Ps[j0 + j]     * GTc[(j0 + j)     * BINS];
            a1 += Ps[j0 + j + 1] * GTc[(j0 + j + 1) * BINS];
            a2 += Ps[j0 + j + 2] * GTc[(j0 + j + 2) * BINS];
            a3 += Ps[j0 + j + 3] * GTc[(j0 + j + 3) * BINS];
        }
        s = (a0 + a1) + (a2 + a3);
    }
    part[g][c] = s;
    __syncthreads();

    if (tid < 64) {
        float t = (part[0][tid] + part[1][tid]) + (part[2][tid] + part[3][tid]);
        if (tid < BINS) g_hgram[(size_t)nb * BINS + tid] = t;
        rows[tid] = (tid < BINS) ? t : 0.0f;
    }
    __syncthreads();
    if (tid < 32) {
        float r = rows[tid] + rows[tid + 32];
#pragma unroll
        for (int o = 16; o; o >>= 1) r += __shfl_xor_sync(0xffffffffu, r, o);
        if (tid == 0) g_mx[nb] = r;
    }

    // ---- last-block tail: marginals + MI ------------------------------------
    __threadfence();
    __shared__ bool isLast;
    if (tid == 0) isLast = (atomicAdd(&g_cnt, 1u) == 399u);
    __syncthreads();
    if (!isLast) return;
    if (tid == 0) g_cnt = 0;           // reset for next graph replay

    __shared__ float myS[NBATCH * BINS];
    __shared__ float red[256];
    __shared__ float sS;

    // column marginals: my[n][c] = sum_b hgram[n][b][c]
    for (int t = tid; t < NBATCH * BINS; t += 256) {
        int n = t / BINS, cc = t % BINS;
        const float* Hn = g_hgram + (size_t)n * BINS * BINS + cc;
        float m = 0.0f;
#pragma unroll 10
        for (int b = 0; b < BINS; b++) m += Hn[(size_t)b * BINS];
        myS[t] = m;
    }
    // grand total from row marginals
    {
        float sacc = 0.0f;
        for (int t = tid; t < NBATCH * BINS; t += 256) sacc += g_mx[t];
        red[tid] = sacc; __syncthreads();
        for (int o = 128; o; o >>= 1) { if (tid < o) red[tid] += red[tid + o]; __syncthreads(); }
        if (tid == 0) sS = red[0];
        __syncthreads();
    }

    float inv = 1.0f / sS;
    float mi = 0.0f;
    const int TOT = NBATCH * BINS * BINS;    // 20000
    for (int t = tid; t < TOT; t += 256) {
        int n = t / (BINS * BINS);
        int rem = t - n * (BINS * BINS);
        int b = rem / BINS, cc = rem % BINS;
        float p = g_hgram[t] * inv;
        float q = (g_mx[n * BINS + b] * inv) * (myS[n * BINS + cc] * inv);
        mi += p * __logf(__fdividef(p + 1e-8f, q + 1e-8f));
    }
    red[tid] = mi; __syncthreads();
    for (int o = 128; o; o >>= 1) { if (tid < o) red[tid] += red[tid + o]; __syncthreads(); }
    if (tid == 0) out[0] = red[0];
}

// ---------------- Launch -------------------------------------------------------
extern "C" void kernel_launch(void* const* d_in, const int* in_sizes, int n_in,
                              void* d_out, int out_size) {
    const float* im1 = (const float*)d_in[0];
    const float* im2 = (const float*)d_in[1];
    k_init  <<<512, 256>>>();
    k_hist  <<<(NBATCH * DPIX / 4 + 255) / 256, 256>>>(im1, im2);
    k_stageC<<<160, 128>>>();
    k_stageD<<<400, 256>>>((float*)d_out);
}

// round 11
// speedup vs baseline: 1.2972x; 1.2972x over previous
#include <cuda_runtime.h>
#include <math.h>

#define NBATCH 8
#define DPIX   147456     // 384*384
#define KBINS  256
#define BINS   50

// Scratch (device globals; no dynamic allocation allowed)
__device__ __align__(16) float g_A[NBATCH * KBINS * KBINS];  // fine 2D histogram (2 MB)
__device__ __align__(16) float g_G [BINS * KBINS];           // G[b][i]
__device__ __align__(16) float g_GT[KBINS * BINS];           // GT[i][b]
__device__ __align__(16) float g_P [2 * NBATCH * BINS * KBINS];  // P halves [is][n][b][j]
__device__ __align__(16) float g_hgram[NBATCH * BINS * BINS];
__device__ float g_mx[NBATCH * BINS];       // row marginals

// ---------------- Kernel 1: nearest-cell 2D histogram + G table + out zero ----
__device__ __forceinline__ void red1(float* p, float a) {
    asm volatile("red.global.add.f32 [%0], %1;" :: "l"(p), "f"(a) : "memory");
}

__global__ void k_hist(const float* __restrict__ im1, const float* __restrict__ im2,
                       float* __restrict__ out) {
    int gid = blockIdx.x * blockDim.x + threadIdx.x;   // one float4 chunk (4 pixels)

    if (gid == 0) out[0] = 0.0f;                       // harness poisons d_out

    // fold G-table computation into the first BINS*KBINS threads
    if (gid < BINS * KBINS) {
        int b = gid / KBINS, i = gid % KBINS;
        float x = (i + 0.5f) * (1.0f / KBINS);
        float c = (b + 0.5f) * 0.02f;
        float d = 10.0f * (x - c);
        float s1 = 1.0f / (1.0f + __expf(-(d + 0.1f)));
        float s2 = 1.0f / (1.0f + __expf(-(d - 0.1f)));
        float v = s1 - s2;
        g_G [b * KBINS + i] = v;
        g_GT[i * BINS  + b] = v;
    }

    const int nchunk = (NBATCH * DPIX) / 4;
    if (gid >= nchunk) return;
    int n = gid / (DPIX / 4);   // 36864 chunks per batch, no straddle
    float4 xv = ((const float4*)im1)[gid];
    float4 yv = ((const float4*)im2)[gid];
    float* base = g_A + (size_t)n * KBINS * KBINS;

    float xs[4] = {xv.x, xv.y, xv.z, xv.w};
    float ys[4] = {yv.x, yv.y, yv.z, yv.w};
#pragma unroll
    for (int q = 0; q < 4; q++) {
        int i0 = min(KBINS - 1, (int)(xs[q] * 256.0f));
        int j0 = min(KBINS - 1, (int)(ys[q] * 256.0f));
        red1(base + i0 * KBINS + j0, 1.0f);
    }
}

// ---------------- Kernel 2: P[is][n][b][j] = sum_{i in half} G[b][i]*H[n][i][j]
// grid = 160 blocks, 128 threads
__global__ void k_stageC() {
    int blk = blockIdx.x;
    int n  = blk / 20;
    int r  = blk % 20;
    int jt = r / 10;
    int r2 = r % 10;
    int bg = r2 / 2, is = r2 % 2;
    int j  = jt * 128 + threadIdx.x;
    int b0 = bg * 10;
    int i_beg = is * 128;

    __shared__ float Gs[64][12];   // 48B rows -> float4-aligned
    float acc[10];
#pragma unroll
    for (int k = 0; k < 10; k++) acc[k] = 0.0f;

    const float* A = g_A + (size_t)n * KBINS * KBINS + j;

    for (int it = i_beg; it < i_beg + 128; it += 64) {
        __syncthreads();
        for (int t = threadIdx.x; t < 640; t += 128) {
            int ii = t / 10, k = t % 10;
            Gs[ii][k] = g_GT[(it + ii) * BINS + b0 + k];
        }
        __syncthreads();
#pragma unroll 8
        for (int ii = 0; ii < 64; ii++) {
            int i = it + ii;
            float h = A[(size_t)i * KBINS];
            float4 ga = *(const float4*)&Gs[ii][0];
            float4 gb = *(const float4*)&Gs[ii][4];
            float2 gc = *(const float2*)&Gs[ii][8];
            acc[0] += h * ga.x; acc[1] += h * ga.y; acc[2] += h * ga.z; acc[3] += h * ga.w;
            acc[4] += h * gb.x; acc[5] += h * gb.y; acc[6] += h * gb.z; acc[7] += h * gb.w;
            acc[8] += h * gc.x; acc[9] += h * gc.y;
        }
    }
    size_t pb = (((size_t)is * NBATCH + n) * BINS + b0) * KBINS + j;
#pragma unroll
    for (int k = 0; k < 10; k++) g_P[pb + (size_t)k * KBINS] = acc[k];
}

// ---------------- Kernel 3: hgram rows + row marginals -------------------------
// grid = 400 (nb = n*50+b), 256 threads: tid = g*64 + c
__global__ void __launch_bounds__(256) k_stageD() {
    int nb = blockIdx.x;
    __shared__ float Ps[KBINS];
    __shared__ float part[4][64];
    __shared__ float rows[64];
    int tid = threadIdx.x;
    int g = tid >> 6, c = tid & 63;

    Ps[tid] = g_P[(size_t)nb * KBINS + tid]
            + g_P[(size_t)(NBATCH * BINS + nb) * KBINS + tid];
    __syncthreads();

    float s = 0.0f;
    if (c < BINS) {
        const float* GTc = g_GT + c;
        int j0 = g * 64;
        float a0 = 0.f, a1 = 0.f, a2 = 0.f, a3 = 0.f;
#pragma unroll
        for (int j = 0; j < 64; j += 4) {
            a0 += Ps[j0 + j]     * GTc[(j0 + j)     * BINS];
            a1 += Ps[j0 + j + 1] * GTc[(j0 + j + 1) * BINS];
            a2 += Ps[j0 + j + 2] * GTc[(j0 + j + 2) * BINS];
            a3 += Ps[j0 + j + 3] * GTc[(j0 + j + 3) * BINS];
        }
        s = (a0 + a1) + (a2 + a3);
    }
    part[g][c] = s;
    __syncthreads();

    if (tid < 64) {
        float t = (part[0][tid] + part[1][tid]) + (part[2][tid] + part[3][tid]);
        if (tid < BINS) g_hgram[(size_t)nb * BINS + tid] = t;
        rows[tid] = (tid < BINS) ? t : 0.0f;
    }
    __syncthreads();
    if (tid < 32) {
        float r = rows[tid] + rows[tid + 32];
#pragma unroll
        for (int o = 16; o; o >>= 1) r += __shfl_xor_sync(0xffffffffu, r, o);
        if (tid == 0) g_mx[nb] = r;
    }
}

// ---------------- Kernel 4: MI terms (self-sufficient: derives S and my) -------
// grid = 400 (nb), 64 threads
__global__ void __launch_bounds__(64) k_stageE(float* __restrict__ out) {
    int nb = blockIdx.x;
    int n  = nb / BINS;
    int tid = threadIdx.x;
    int c  = tid;

    // grand total S from row marginals (coalesced, per-block)
    __shared__ float sS;
    __shared__ float wred[2];
    float sacc = 0.0f;
    for (int t = tid; t < NBATCH * BINS; t += 64) sacc += g_mx[t];
#pragma unroll
    for (int o = 16; o; o >>= 1) sacc += __shfl_xor_sync(0xffffffffu, sacc, o);
    if ((tid & 31) == 0) wred[tid >> 5] = sacc;
    __syncthreads();
    if (tid == 0) sS = wred[0] + wred[1];
    __syncthreads();

    float mi = 0.0f;
    if (c < BINS) {
        // column marginal my[n][c] = sum_b hgram[n][b][c]  (L2-resident)
        const float* Hn = g_hgram + (size_t)n * BINS * BINS + c;
        float m0 = 0.f, m1 = 0.f;
#pragma unroll 5
        for (int b = 0; b < BINS; b += 2) {
            m0 += Hn[(size_t)b * BINS];
            m1 += Hn[(size_t)(b + 1) * BINS];
        }
        float my = m0 + m1;
        float inv = 1.0f / sS;
        float p = g_hgram[(size_t)nb * BINS + c] * inv;
        float q = (g_mx[nb] * inv) * (my * inv);
        mi = p * __logf(__fdividef(p + 1e-8f, q + 1e-8f));
    }
#pragma unroll
    for (int o = 16; o; o >>= 1) mi += __shfl_xor_sync(0xffffffffu, mi, o);
    if ((tid & 31) == 0) wred[tid >> 5] = mi;
    __syncthreads();
    if (tid == 0) atomicAdd(out, wred[0] + wred[1]);
}

// ---------------- Launch -------------------------------------------------------
extern "C" void kernel_launch(void* const* d_in, const int* in_sizes, int n_in,
                              void* d_out, int out_size) {
    const float* im1 = (const float*)d_in[0];
    const float* im2 = (const float*)d_in[1];

    void* aPtr = nullptr;
    cudaGetSymbolAddress(&aPtr, g_A);
    cudaMemsetAsync(aPtr, 0, sizeof(float) * NBATCH * KBINS * KBINS);

    k_hist  <<<(NBATCH * DPIX / 4 + 255) / 256, 256>>>(im1, im2, (float*)d_out);
    k_stageC<<<160, 128>>>();
    k_stageD<<<400, 256>>>();
    k_stageE<<<400, 64>>>((float*)d_out);
}